// round 13
// baseline (speedup 1.0000x reference)
#include <cuda_runtime.h>
#include <cstdint>

#define NN   100000
#define NE   3200000
#define FIN  128
#define HID  16
#define ND   2000
#define BMW  3125            // bitmask words = ceil(NN/32)
#define CAP  128             // bucket capacity (max in-degree ~70 for Poisson(32))
#define CK   16              // gemm1 k-chunk
#define XST  20              // xs row stride: 80B (16B-aligned) AND conflict-free LDS.128
#define FULLMASK 0xffffffffu

// ---------------- scratch (no allocs allowed) ----------------
__device__ __align__(16) int      g_cnt [NN];        // in-degree counters / bucket cursors
__device__ __align__(16) float    g_hs  [NN * HID];  // dinv-scaled features (gather source)
__device__ __align__(16) float    g_agg [NN * HID];  // aggregated layer output
__device__ __align__(16) unsigned g_bm  [BMW];       // node mask bitset
__device__ __align__(16) int      g_mlist[NN];       // dense masked-node worklist
__device__ int g_mcnt;
__device__ __align__(16) int      g_bkt [NN * CAP];  // per-dst src buckets
__device__ __align__(16) int2     g_list2[NE / 8];   // edges with dst < ND (~64k)
__device__ int g_cnt2;
__device__ __align__(16) float    g_h2  [ND * HID];
__device__ __align__(16) float    g_tmp [ND * HID];

// ---------------- f32x2 helpers ----------------
__device__ __forceinline__ unsigned long long pack2(float v) {
    unsigned long long r;
    unsigned u = __float_as_uint(v);
    asm("mov.b64 %0, {%1, %1};" : "=l"(r) : "r"(u));
    return r;
}
__device__ __forceinline__ unsigned long long ffma2(unsigned long long a,
                                                    unsigned long long b,
                                                    unsigned long long c) {
    unsigned long long d;
    asm("fma.rn.f32x2 %0, %1, %2, %3;" : "=l"(d) : "l"(a), "l"(b), "l"(c));
    return d;
}
__device__ __forceinline__ float2 unpack2(unsigned long long v) {
    unsigned lo, hi;
    asm("mov.b64 {%0, %1}, %2;" : "=r"(lo), "=r"(hi) : "l"(v));
    return make_float2(__uint_as_float(lo), __uint_as_float(hi));
}
__device__ __forceinline__ unsigned smem_u32(const void* p) {
    return (unsigned)__cvta_generic_to_shared(p);
}

// ---------------- init: cnt=0, bm/mlist pre-seeded with drug nodes ----------------
__global__ void k_init() {
    int i = blockIdx.x * 256 + threadIdx.x;
    if (i < NN) g_cnt[i] = 0;
    if (i < BMW) g_bm[i] = (i < 62) ? ~0u : ((i == 62) ? 0x0000FFFFu : 0u);
    if (i < ND) g_mlist[i] = i;
    if (i == 0) { g_cnt2 = 0; g_mcnt = ND; }
}

// ---------------- single edge pass: buckets + degree + mask list + drug list ----------------
__global__ void k_prep2(const int* __restrict__ src, const int* __restrict__ dst) {
    int e = blockIdx.x * 256 + threadIdx.x;          // grid covers NE exactly
    int lane = threadIdx.x & 31;
    int d = __ldg(dst + e);
    int s = __ldg(src + e);

    int pos = atomicAdd(&g_cnt[d], 1);               // cursor == in-degree counter
    if (pos < CAP) g_bkt[(size_t)d * CAP + pos] = s;

    bool take2 = (d < ND);
    if (take2) {
        unsigned bit = 1u << (s & 31);
        unsigned old = atomicOr(g_bm + (s >> 5), bit);
        if (!(old & bit)) {                          // exactly-once dense append
            int mp = atomicAdd(&g_mcnt, 1);
            g_mlist[mp] = s;
        }
    }
    unsigned b2 = __ballot_sync(FULLMASK, take2);
    if (b2) {
        int leader = __ffs(b2) - 1;
        int p = 0;
        if (lane == leader) p = atomicAdd(&g_cnt2, __popc(b2));
        p = __shfl_sync(FULLMASK, p, leader);
        if (take2) g_list2[p + __popc(b2 & ((1u << lane) - 1))] = make_int2(s, d);
    }
}

// ---------------- GEMM1: g_hs = rsqrt(deg) * (x @ W1) ----------------
// 1 thread = 1 node. x staged via cp.async double-buffered 16-k chunks;
// W rows warp-uniform broadcast; packed f32x2 FMA.
__global__ void __launch_bounds__(256) k_gemm1(const float* __restrict__ x,
                                               const float* __restrict__ W1) {
    __shared__ __align__(16) float W1s[FIN * HID];      // 8 KB
    __shared__ __align__(16) float xs[2][256 * XST];    // 2 x 20 KB
    int tid = threadIdx.x;
    int nbase = blockIdx.x * 256;
    int node = nbase + tid;

    for (int i = tid; i < FIN * HID / 4; i += 256)
        reinterpret_cast<float4*>(W1s)[i] = reinterpret_cast<const float4*>(W1)[i];

    auto stage = [&](int c, int b) {
#pragma unroll
        for (int it = 0; it < 4; it++) {
            int idx = tid + it * 256;
            int row = idx >> 2, f4 = idx & 3;
            if (nbase + row < NN) {
                const float* gp = x + (size_t)(nbase + row) * FIN + c * CK + f4 * 4;
                unsigned sp = smem_u32(&xs[b][row * XST + f4 * 4]);   // 16B-aligned
                asm volatile("cp.async.ca.shared.global [%0], [%1], 16;"
                             :: "r"(sp), "l"(gp));
            }
        }
        asm volatile("cp.async.commit_group;");
    };

    unsigned long long acc2[8];
#pragma unroll
    for (int j = 0; j < 8; j++) acc2[j] = 0ull;

    stage(0, 0);

#pragma unroll 1
    for (int c = 0; c < FIN / CK; c++) {
        if (c + 1 < FIN / CK) {
            stage(c + 1, (c + 1) & 1);
            asm volatile("cp.async.wait_group 1;");
        } else {
            asm volatile("cp.async.wait_group 0;");
        }
        __syncthreads();
        const float* xrow = &xs[c & 1][tid * XST];
#pragma unroll
        for (int k4 = 0; k4 < 4; k4++) {
            float4 xv4 = *reinterpret_cast<const float4*>(xrow + k4 * 4);
            float xv[4] = {xv4.x, xv4.y, xv4.z, xv4.w};
#pragma unroll
            for (int q = 0; q < 4; q++) {
                int k = c * CK + k4 * 4 + q;
                unsigned long long xv2 = pack2(xv[q]);
                const ulonglong2* wr = reinterpret_cast<const ulonglong2*>(W1s + k * HID);
                ulonglong2 wa = wr[0], wb = wr[1];
                acc2[0] = ffma2(xv2, wa.x, acc2[0]);
                acc2[1] = ffma2(xv2, wa.y, acc2[1]);
                acc2[2] = ffma2(xv2, wb.x, acc2[2]);
                acc2[3] = ffma2(xv2, wb.y, acc2[3]);
                ulonglong2 wc = wr[2], wd = wr[3];
                acc2[4] = ffma2(xv2, wc.x, acc2[4]);
                acc2[5] = ffma2(xv2, wc.y, acc2[5]);
                acc2[6] = ffma2(xv2, wd.x, acc2[6]);
                acc2[7] = ffma2(xv2, wd.y, acc2[7]);
            }
        }
        __syncthreads();   // protect buffer (c&1) before re-staging
    }
    if (node >= NN) return;
    float di = rsqrtf((float)g_cnt[node] + 1.0f);    // +1 self loop
#pragma unroll
    for (int q = 0; q < 4; q++) {
        float2 a = unpack2(acc2[q * 2]);
        float2 b = unpack2(acc2[q * 2 + 1]);
        float4 v = make_float4(a.x * di, a.y * di, b.x * di, b.y * di);
        *reinterpret_cast<float4*>(g_hs + (size_t)node * HID + q * 4) = v;
    }
}

// ---------------- gather over dense worklist: index-prefetch pipelined ----------------
// 4 lanes per masked node, each owns 4 cols. Next iteration's index int4s are
// prefetched before consuming the current ones, overlapping idx latency with gathers.
__global__ void k_gather() {
    int total = g_mcnt * 4;
    int t = blockIdx.x * 256 + threadIdx.x;
    if (t >= total) return;
    int n = g_mlist[t >> 2];
    int c = (t & 3) * 4;
    int cnt = g_cnt[n];
    if (cnt > CAP) cnt = CAP;
    const int* b = g_bkt + (size_t)n * CAP;

    float4 acc = *reinterpret_cast<const float4*>(g_hs + (size_t)n * HID + c); // self

    int i = 0;
    if (cnt >= 8) {
        int4 p0 = *reinterpret_cast<const int4*>(b);
        int4 p1 = *reinterpret_cast<const int4*>(b + 4);
        while (true) {
            int4 c0 = p0, c1 = p1;
            int next = i + 8;
            bool more = (next + 8 <= cnt);
            if (more) {                               // prefetch next indices NOW
                p0 = *reinterpret_cast<const int4*>(b + next);
                p1 = *reinterpret_cast<const int4*>(b + next + 4);
            }
            float4 a0 = *reinterpret_cast<const float4*>(g_hs + (size_t)c0.x * HID + c);
            float4 a1 = *reinterpret_cast<const float4*>(g_hs + (size_t)c0.y * HID + c);
            float4 a2 = *reinterpret_cast<const float4*>(g_hs + (size_t)c0.z * HID + c);
            float4 a3 = *reinterpret_cast<const float4*>(g_hs + (size_t)c0.w * HID + c);
            float4 a4 = *reinterpret_cast<const float4*>(g_hs + (size_t)c1.x * HID + c);
            float4 a5 = *reinterpret_cast<const float4*>(g_hs + (size_t)c1.y * HID + c);
            float4 a6 = *reinterpret_cast<const float4*>(g_hs + (size_t)c1.z * HID + c);
            float4 a7 = *reinterpret_cast<const float4*>(g_hs + (size_t)c1.w * HID + c);
            acc.x += (a0.x + a1.x) + (a2.x + a3.x) + (a4.x + a5.x) + (a6.x + a7.x);
            acc.y += (a0.y + a1.y) + (a2.y + a3.y) + (a4.y + a5.y) + (a6.y + a7.y);
            acc.z += (a0.z + a1.z) + (a2.z + a3.z) + (a4.z + a5.z) + (a6.z + a7.z);
            acc.w += (a0.w + a1.w) + (a2.w + a3.w) + (a4.w + a5.w) + (a6.w + a7.w);
            i = next;
            if (!more) break;
        }
    }
    if (i + 4 <= cnt) {                               // 4-wide tail
        int4 c0 = *reinterpret_cast<const int4*>(b + i);
        float4 a0 = *reinterpret_cast<const float4*>(g_hs + (size_t)c0.x * HID + c);
        float4 a1 = *reinterpret_cast<const float4*>(g_hs + (size_t)c0.y * HID + c);
        float4 a2 = *reinterpret_cast<const float4*>(g_hs + (size_t)c0.z * HID + c);
        float4 a3 = *reinterpret_cast<const float4*>(g_hs + (size_t)c0.w * HID + c);
        acc.x += (a0.x + a1.x) + (a2.x + a3.x);
        acc.y += (a0.y + a1.y) + (a2.y + a3.y);
        acc.z += (a0.z + a1.z) + (a2.z + a3.z);
        acc.w += (a0.w + a1.w) + (a2.w + a3.w);
        i += 4;
    }
    for (; i < cnt; i++) {                            // scalar tail (<=3)
        int s0 = __ldg(b + i);
        float4 a = *reinterpret_cast<const float4*>(g_hs + (size_t)s0 * HID + c);
        acc.x += a.x; acc.y += a.y; acc.z += a.z; acc.w += a.w;
    }
    *reinterpret_cast<float4*>(g_agg + (size_t)n * HID + c) = acc;
}

// ---------------- edge pass 2: compacted drug-edge list (REDs; ~64k edges) ----------------
__global__ void k_edge2() {
    int total = g_cnt2 * 4;
    const int stride = gridDim.x * 256;
    for (int i = blockIdx.x * 256 + threadIdx.x; i < total; i += stride) {
        int e = i >> 2;
        int c = (i & 3) * 4;
        int2 sd = __ldg(&g_list2[e]);
        float4 v = *reinterpret_cast<const float4*>(g_hs + (size_t)sd.x * HID + c);
        float* p = g_agg + (size_t)sd.y * HID + c;
        asm volatile("red.global.add.v4.f32 [%0], {%1,%2,%3,%4};"
                     :: "l"(__cvta_generic_to_global(p)),
                        "f"(v.x), "f"(v.y), "f"(v.z), "f"(v.w)
                     : "memory");
    }
}

// ---------------- GEMM2 over dense worklist: g_hs = dinv*( relu(dinv*agg1+b1) @ W2 ) ----------------
__global__ void k_gemm2(const float* __restrict__ W2, const float* __restrict__ b1) {
    __shared__ float W2s[HID * HID];
    __shared__ float b1s[HID];
    int tid = threadIdx.x;
    W2s[tid] = W2[tid];
    if (tid < HID) b1s[tid] = b1[tid];
    __syncthreads();
    int idx = blockIdx.x * 256 + tid;
    if (idx >= g_mcnt) return;
    int n = g_mlist[idx];

    float di = rsqrtf((float)g_cnt[n] + 1.0f);
    float row[HID];
    const float4* rv = reinterpret_cast<const float4*>(g_agg + (size_t)n * HID);
#pragma unroll
    for (int q = 0; q < 4; q++) {
        float4 v = rv[q];
        row[q * 4 + 0] = fmaxf(di * v.x + b1s[q * 4 + 0], 0.f);
        row[q * 4 + 1] = fmaxf(di * v.y + b1s[q * 4 + 1], 0.f);
        row[q * 4 + 2] = fmaxf(di * v.z + b1s[q * 4 + 2], 0.f);
        row[q * 4 + 3] = fmaxf(di * v.w + b1s[q * 4 + 3], 0.f);
    }
    float4 acc[4];
#pragma unroll
    for (int q = 0; q < 4; q++) acc[q] = make_float4(0.f, 0.f, 0.f, 0.f);
#pragma unroll
    for (int k = 0; k < HID; k++) {
        float hv = row[k];
#pragma unroll
        for (int q = 0; q < 4; q++) {
            float4 w = *reinterpret_cast<const float4*>(W2s + k * HID + q * 4);
            acc[q].x += hv * w.x; acc[q].y += hv * w.y;
            acc[q].z += hv * w.z; acc[q].w += hv * w.w;
        }
    }
#pragma unroll
    for (int q = 0; q < 4; q++) {
        acc[q].x *= di; acc[q].y *= di; acc[q].z *= di; acc[q].w *= di;
        *reinterpret_cast<float4*>(g_hs + (size_t)n * HID + q * 4) = acc[q];
        if (n < ND)
            *reinterpret_cast<float4*>(g_agg + (size_t)n * HID + q * 4) = acc[q]; // self term
    }
}

// ---------------- finalize layer 2 + tmp = h2 @ P ----------------
__global__ void k_pred1(const float* __restrict__ P, const float* __restrict__ b2) {
    __shared__ float Ps[HID * HID];
    __shared__ float h2s[16][17];
    int tid = threadIdx.x;
    Ps[tid] = P[tid];
    int gid = blockIdx.x * 256 + tid;      // < ND*HID
    int i = gid >> 4, j = gid & 15;
    int il = tid >> 4, jl = tid & 15;
    float v = rsqrtf((float)g_cnt[i] + 1.0f) * g_agg[gid] + __ldg(b2 + j);
    g_h2[gid] = v;
    h2s[il][jl] = v;
    __syncthreads();
    float acc = 0.f;
#pragma unroll
    for (int k = 0; k < HID; k++) acc += h2s[il][k] * Ps[k * HID + j];
    g_tmp[gid] = acc;
}

// ---------------- out: 32x32 tile / block, 2x2 per thread (bounds-guarded) ----------------
__global__ void k_out(float* __restrict__ out) {
    __shared__ float ts[32][17];
    __shared__ float hs[32][17];
    int tid = threadIdx.x;
    int ib = blockIdx.y * 32, jb = blockIdx.x * 32;
    {
        int r = tid >> 3;
        int c2 = (tid & 7) * 2;
        float2 tv = (ib + r < ND)
            ? *reinterpret_cast<const float2*>(g_tmp + (size_t)(ib + r) * HID + c2)
            : make_float2(0.f, 0.f);
        float2 hv = (jb + r < ND)
            ? *reinterpret_cast<const float2*>(g_h2 + (size_t)(jb + r) * HID + c2)
            : make_float2(0.f, 0.f);
        ts[r][c2] = tv.x; ts[r][c2 + 1] = tv.y;
        hs[r][c2] = hv.x; hs[r][c2 + 1] = hv.y;
    }
    __syncthreads();
    int ty = tid >> 4, tx = tid & 15;
    float a00 = 0.f, a01 = 0.f, a10 = 0.f, a11 = 0.f;
#pragma unroll
    for (int k = 0; k < HID; k++) {
        float t0 = ts[ty][k], t1 = ts[ty + 16][k];
        float h0 = hs[tx][k], h1 = hs[tx + 16][k];
        a00 += t0 * h0; a01 += t0 * h1;
        a10 += t1 * h0; a11 += t1 * h1;
    }
    int i0 = ib + ty, i1 = ib + ty + 16;
    int j0 = jb + tx, j1 = jb + tx + 16;
    if (i0 < ND) {
        if (j0 < ND) out[(size_t)i0 * ND + j0] = a00;
        if (j1 < ND) out[(size_t)i0 * ND + j1] = a01;
    }
    if (i1 < ND) {
        if (j0 < ND) out[(size_t)i1 * ND + j0] = a10;
        if (j1 < ND) out[(size_t)i1 * ND + j1] = a11;
    }
}

// ---------------- launch ----------------
extern "C" void kernel_launch(void* const* d_in, const int* in_sizes, int n_in,
                              void* d_out, int out_size) {
    (void)in_sizes; (void)n_in; (void)out_size;
    const float* x  = (const float*)d_in[0];
    const int*   ei = (const int*)  d_in[1];
    const float* W1 = (const float*)d_in[2];
    const float* b1 = (const float*)d_in[3];
    const float* W2 = (const float*)d_in[4];
    const float* b2 = (const float*)d_in[5];
    const float* P  = (const float*)d_in[6];
    float* out = (float*)d_out;

    const int* src = ei;
    const int* dst = ei + NE;

    k_init <<<(NN + 255) / 256, 256>>>();
    k_prep2<<<NE / 256, 256>>>(src, dst);

    // layer 1
    k_gemm1 <<<(NN + 255) / 256, 256>>>(x, W1);
    k_gather<<<(NN * 4 + 255) / 256, 256>>>();   // early-exits past g_mcnt*4

    // layer 2
    k_gemm2<<<(NN + 255) / 256, 256>>>(W2, b1);  // early-exits past g_mcnt
    k_edge2<<<256, 256>>>();

    // decoder
    k_pred1<<<(ND * HID) / 256, 256>>>(P, b2);
    k_out  <<<dim3((ND + 31) / 32, (ND + 31) / 32), 256>>>(out);
}

// round 15
// speedup vs baseline: 1.0582x; 1.0582x over previous
#include <cuda_runtime.h>
#include <cstdint>

#define NN   100000
#define NE   3200000
#define FIN  128
#define HID  16
#define ND   2000
#define BMW  3125            // bitmask words = ceil(NN/32)
#define CAP  128             // bucket capacity (max in-degree ~70 for Poisson(32))
#define CK   16              // gemm1 k-chunk
#define XST  20              // xs row stride: 80B (16B-aligned) AND conflict-free LDS.128
#define FULLMASK 0xffffffffu

// ---------------- scratch (no allocs allowed) ----------------
__device__ __align__(16) int      g_cnt [NN];        // in-degree counters / bucket cursors
__device__ __align__(16) float    g_hs  [NN * HID];  // layer-1 dinv-scaled features (gather src)
__device__ __align__(16) float    g_hs2 [NN * HID];  // layer-2 dinv-scaled features (NO alias!)
__device__ __align__(16) float    g_agg [NN * HID];  // aggregated layer-2 output (drug rows)
__device__ __align__(16) unsigned g_bm  [BMW];       // node mask bitset
__device__ __align__(16) int      g_mlist[NN];       // dense masked-node worklist
__device__ int g_mcnt;
__device__ __align__(16) int      g_bkt [NN * CAP];  // per-dst src buckets
__device__ __align__(16) int2     g_list2[NE / 8];   // edges with dst < ND (~64k)
__device__ int g_cnt2;
__device__ __align__(16) float    g_h2  [ND * HID];
__device__ __align__(16) float    g_tmp [ND * HID];

// ---------------- f32x2 helpers ----------------
__device__ __forceinline__ unsigned long long pack2(float v) {
    unsigned long long r;
    unsigned u = __float_as_uint(v);
    asm("mov.b64 %0, {%1, %1};" : "=l"(r) : "r"(u));
    return r;
}
__device__ __forceinline__ unsigned long long ffma2(unsigned long long a,
                                                    unsigned long long b,
                                                    unsigned long long c) {
    unsigned long long d;
    asm("fma.rn.f32x2 %0, %1, %2, %3;" : "=l"(d) : "l"(a), "l"(b), "l"(c));
    return d;
}
__device__ __forceinline__ float2 unpack2(unsigned long long v) {
    unsigned lo, hi;
    asm("mov.b64 {%0, %1}, %2;" : "=r"(lo), "=r"(hi) : "l"(v));
    return make_float2(__uint_as_float(lo), __uint_as_float(hi));
}
__device__ __forceinline__ unsigned smem_u32(const void* p) {
    return (unsigned)__cvta_generic_to_shared(p);
}

// ---------------- init: cnt=0, bm/mlist pre-seeded with drug nodes ----------------
__global__ void k_init() {
    int i = blockIdx.x * 256 + threadIdx.x;
    if (i < NN) g_cnt[i] = 0;
    if (i < BMW) g_bm[i] = (i < 62) ? ~0u : ((i == 62) ? 0x0000FFFFu : 0u);
    if (i < ND) g_mlist[i] = i;
    if (i == 0) { g_cnt2 = 0; g_mcnt = ND; }
}

// ---------------- single edge pass: buckets + degree + mask list + drug list ----------------
__global__ void k_prep2(const int* __restrict__ src, const int* __restrict__ dst) {
    int e = blockIdx.x * 256 + threadIdx.x;          // grid covers NE exactly
    int lane = threadIdx.x & 31;
    int d = __ldg(dst + e);
    int s = __ldg(src + e);

    int pos = atomicAdd(&g_cnt[d], 1);               // cursor == in-degree counter
    if (pos < CAP) g_bkt[(size_t)d * CAP + pos] = s;

    bool take2 = (d < ND);
    if (take2) {
        unsigned bit = 1u << (s & 31);
        unsigned old = atomicOr(g_bm + (s >> 5), bit);
        if (!(old & bit)) {                          // exactly-once dense append
            int mp = atomicAdd(&g_mcnt, 1);
            g_mlist[mp] = s;
        }
    }
    unsigned b2 = __ballot_sync(FULLMASK, take2);
    if (b2) {
        int leader = __ffs(b2) - 1;
        int p = 0;
        if (lane == leader) p = atomicAdd(&g_cnt2, __popc(b2));
        p = __shfl_sync(FULLMASK, p, leader);
        if (take2) g_list2[p + __popc(b2 & ((1u << lane) - 1))] = make_int2(s, d);
    }
}

// ---------------- GEMM1: g_hs = rsqrt(deg) * (x @ W1) ----------------
// 1 thread = 1 node. x staged via cp.async double-buffered 16-k chunks;
// W rows warp-uniform broadcast; packed f32x2 FMA.
__global__ void __launch_bounds__(256) k_gemm1(const float* __restrict__ x,
                                               const float* __restrict__ W1) {
    __shared__ __align__(16) float W1s[FIN * HID];      // 8 KB
    __shared__ __align__(16) float xs[2][256 * XST];    // 2 x 20 KB
    int tid = threadIdx.x;
    int nbase = blockIdx.x * 256;
    int node = nbase + tid;

    for (int i = tid; i < FIN * HID / 4; i += 256)
        reinterpret_cast<float4*>(W1s)[i] = reinterpret_cast<const float4*>(W1)[i];

    auto stage = [&](int c, int b) {
#pragma unroll
        for (int it = 0; it < 4; it++) {
            int idx = tid + it * 256;
            int row = idx >> 2, f4 = idx & 3;
            if (nbase + row < NN) {
                const float* gp = x + (size_t)(nbase + row) * FIN + c * CK + f4 * 4;
                unsigned sp = smem_u32(&xs[b][row * XST + f4 * 4]);   // 16B-aligned
                asm volatile("cp.async.ca.shared.global [%0], [%1], 16;"
                             :: "r"(sp), "l"(gp));
            }
        }
        asm volatile("cp.async.commit_group;");
    };

    unsigned long long acc2[8];
#pragma unroll
    for (int j = 0; j < 8; j++) acc2[j] = 0ull;

    stage(0, 0);

#pragma unroll 1
    for (int c = 0; c < FIN / CK; c++) {
        if (c + 1 < FIN / CK) {
            stage(c + 1, (c + 1) & 1);
            asm volatile("cp.async.wait_group 1;");
        } else {
            asm volatile("cp.async.wait_group 0;");
        }
        __syncthreads();
        const float* xrow = &xs[c & 1][tid * XST];
#pragma unroll
        for (int k4 = 0; k4 < 4; k4++) {
            float4 xv4 = *reinterpret_cast<const float4*>(xrow + k4 * 4);
            float xv[4] = {xv4.x, xv4.y, xv4.z, xv4.w};
#pragma unroll
            for (int q = 0; q < 4; q++) {
                int k = c * CK + k4 * 4 + q;
                unsigned long long xv2 = pack2(xv[q]);
                const ulonglong2* wr = reinterpret_cast<const ulonglong2*>(W1s + k * HID);
                ulonglong2 wa = wr[0], wb = wr[1];
                acc2[0] = ffma2(xv2, wa.x, acc2[0]);
                acc2[1] = ffma2(xv2, wa.y, acc2[1]);
                acc2[2] = ffma2(xv2, wb.x, acc2[2]);
                acc2[3] = ffma2(xv2, wb.y, acc2[3]);
                ulonglong2 wc = wr[2], wd = wr[3];
                acc2[4] = ffma2(xv2, wc.x, acc2[4]);
                acc2[5] = ffma2(xv2, wc.y, acc2[5]);
                acc2[6] = ffma2(xv2, wd.x, acc2[6]);
                acc2[7] = ffma2(xv2, wd.y, acc2[7]);
            }
        }
        __syncthreads();   // protect buffer (c&1) before re-staging
    }
    if (node >= NN) return;
    float di = rsqrtf((float)g_cnt[node] + 1.0f);    // +1 self loop
#pragma unroll
    for (int q = 0; q < 4; q++) {
        float2 a = unpack2(acc2[q * 2]);
        float2 b = unpack2(acc2[q * 2 + 1]);
        float4 v = make_float4(a.x * di, a.y * di, b.x * di, b.y * di);
        *reinterpret_cast<float4*>(g_hs + (size_t)node * HID + q * 4) = v;
    }
}

// ---------------- FUSED gather + GEMM2 over dense worklist ----------------
// Reads ONLY g_hs (layer-1); writes g_hs2 (layer-2) — no aliasing, no race.
// 4 lanes per masked node. After bucket-walk aggregation, the 4-lane group
// exchanges relu'd chunks via SHFL.XOR; each lane computes 4 cols of row@W2.
__global__ void __launch_bounds__(256) k_gather_g2(const float* __restrict__ W2,
                                                   const float* __restrict__ b1) {
    __shared__ float W2s[HID * HID];
    __shared__ float b1s[HID];
    int tid = threadIdx.x;
    W2s[tid] = W2[tid];
    if (tid < HID) b1s[tid] = b1[tid];
    __syncthreads();

    int total = g_mcnt * 4;
    int t = blockIdx.x * 256 + tid;
    if ((t & ~31) >= total) return;                  // warp-uniform exit: shuffles stay full-warp
    bool valid = t < total;
    int tc = valid ? t : (total - 1);                // clamp (group-of-4 aligned: no mixed groups)
    int n = g_mlist[tc >> 2];
    int quad = t & 3;
    int c = quad * 4;
    int cnt = g_cnt[n];
    float di = rsqrtf((float)cnt + 1.0f);
    if (cnt > CAP) cnt = CAP;
    const int* b = g_bkt + (size_t)n * CAP;

    float4 acc = *reinterpret_cast<const float4*>(g_hs + (size_t)n * HID + c); // self
    int i = 0;
    for (; i + 8 <= cnt; i += 8) {
        int4 s0 = *reinterpret_cast<const int4*>(b + i);
        int4 s1 = *reinterpret_cast<const int4*>(b + i + 4);
        float4 a0 = *reinterpret_cast<const float4*>(g_hs + (size_t)s0.x * HID + c);
        float4 a1 = *reinterpret_cast<const float4*>(g_hs + (size_t)s0.y * HID + c);
        float4 a2 = *reinterpret_cast<const float4*>(g_hs + (size_t)s0.z * HID + c);
        float4 a3 = *reinterpret_cast<const float4*>(g_hs + (size_t)s0.w * HID + c);
        float4 a4 = *reinterpret_cast<const float4*>(g_hs + (size_t)s1.x * HID + c);
        float4 a5 = *reinterpret_cast<const float4*>(g_hs + (size_t)s1.y * HID + c);
        float4 a6 = *reinterpret_cast<const float4*>(g_hs + (size_t)s1.z * HID + c);
        float4 a7 = *reinterpret_cast<const float4*>(g_hs + (size_t)s1.w * HID + c);
        acc.x += (a0.x + a1.x) + (a2.x + a3.x) + (a4.x + a5.x) + (a6.x + a7.x);
        acc.y += (a0.y + a1.y) + (a2.y + a3.y) + (a4.y + a5.y) + (a6.y + a7.y);
        acc.z += (a0.z + a1.z) + (a2.z + a3.z) + (a4.z + a5.z) + (a6.z + a7.z);
        acc.w += (a0.w + a1.w) + (a2.w + a3.w) + (a4.w + a5.w) + (a6.w + a7.w);
    }
    for (; i < cnt; i++) {
        int s0 = __ldg(b + i);
        float4 a = *reinterpret_cast<const float4*>(g_hs + (size_t)s0 * HID + c);
        acc.x += a.x; acc.y += a.y; acc.z += a.z; acc.w += a.w;
    }

    // relu(di*agg + b1) for this lane's 4-col chunk
    float4 r;
    r.x = fmaxf(di * acc.x + b1s[c + 0], 0.f);
    r.y = fmaxf(di * acc.y + b1s[c + 1], 0.f);
    r.z = fmaxf(di * acc.z + b1s[c + 2], 0.f);
    r.w = fmaxf(di * acc.w + b1s[c + 3], 0.f);

    // assemble full 16-element relu row via group-of-4 SHFL.XOR exchange
    float row[HID];
    row[c + 0] = r.x; row[c + 1] = r.y; row[c + 2] = r.z; row[c + 3] = r.w;
#pragma unroll
    for (int xm = 1; xm < 4; xm++) {
        int pq = (quad ^ xm) * 4;                    // partner lane's chunk position
        row[pq + 0] = __shfl_xor_sync(FULLMASK, r.x, xm);
        row[pq + 1] = __shfl_xor_sync(FULLMASK, r.y, xm);
        row[pq + 2] = __shfl_xor_sync(FULLMASK, r.z, xm);
        row[pq + 3] = __shfl_xor_sync(FULLMASK, r.w, xm);
    }

    // this lane's 4 output cols of row @ W2 (quadrant LDS.128: broadcast/conflict-free)
    float4 o = make_float4(0.f, 0.f, 0.f, 0.f);
#pragma unroll
    for (int k = 0; k < HID; k++) {
        float hv = row[k];
        float4 w = *reinterpret_cast<const float4*>(W2s + k * HID + c);
        o.x += hv * w.x; o.y += hv * w.y; o.z += hv * w.z; o.w += hv * w.w;
    }
    o.x *= di; o.y *= di; o.z *= di; o.w *= di;

    if (valid) {
        *reinterpret_cast<float4*>(g_hs2 + (size_t)n * HID + c) = o;       // layer-2 buffer
        if (n < ND)
            *reinterpret_cast<float4*>(g_agg + (size_t)n * HID + c) = o;   // self term
    }
}

// ---------------- edge pass 2: drug-edge list REDs; reads g_hs2 ----------------
__global__ void k_edge2() {
    int total = g_cnt2 * 4;
    const int stride = gridDim.x * 256;
    for (int i = blockIdx.x * 256 + threadIdx.x; i < total; i += stride) {
        int e = i >> 2;
        int c = (i & 3) * 4;
        int2 sd = __ldg(&g_list2[e]);
        float4 v = *reinterpret_cast<const float4*>(g_hs2 + (size_t)sd.x * HID + c);
        float* p = g_agg + (size_t)sd.y * HID + c;
        asm volatile("red.global.add.v4.f32 [%0], {%1,%2,%3,%4};"
                     :: "l"(__cvta_generic_to_global(p)),
                        "f"(v.x), "f"(v.y), "f"(v.z), "f"(v.w)
                     : "memory");
    }
}

// ---------------- finalize layer 2 + tmp = h2 @ P ----------------
__global__ void k_pred1(const float* __restrict__ P, const float* __restrict__ b2) {
    __shared__ float Ps[HID * HID];
    __shared__ float h2s[16][17];
    int tid = threadIdx.x;
    Ps[tid] = P[tid];
    int gid = blockIdx.x * 256 + tid;      // < ND*HID
    int i = gid >> 4, j = gid & 15;
    int il = tid >> 4, jl = tid & 15;
    float v = rsqrtf((float)g_cnt[i] + 1.0f) * g_agg[gid] + __ldg(b2 + j);
    g_h2[gid] = v;
    h2s[il][jl] = v;
    __syncthreads();
    float acc = 0.f;
#pragma unroll
    for (int k = 0; k < HID; k++) acc += h2s[il][k] * Ps[k * HID + j];
    g_tmp[gid] = acc;
}

// ---------------- out: 32x32 tile / block, 2x2 per thread (bounds-guarded) ----------------
__global__ void k_out(float* __restrict__ out) {
    __shared__ float ts[32][17];
    __shared__ float hs[32][17];
    int tid = threadIdx.x;
    int ib = blockIdx.y * 32, jb = blockIdx.x * 32;
    {
        int r = tid >> 3;
        int c2 = (tid & 7) * 2;
        float2 tv = (ib + r < ND)
            ? *reinterpret_cast<const float2*>(g_tmp + (size_t)(ib + r) * HID + c2)
            : make_float2(0.f, 0.f);
        float2 hv = (jb + r < ND)
            ? *reinterpret_cast<const float2*>(g_h2 + (size_t)(jb + r) * HID + c2)
            : make_float2(0.f, 0.f);
        ts[r][c2] = tv.x; ts[r][c2 + 1] = tv.y;
        hs[r][c2] = hv.x; hs[r][c2 + 1] = hv.y;
    }
    __syncthreads();
    int ty = tid >> 4, tx = tid & 15;
    float a00 = 0.f, a01 = 0.f, a10 = 0.f, a11 = 0.f;
#pragma unroll
    for (int k = 0; k < HID; k++) {
        float t0 = ts[ty][k], t1 = ts[ty + 16][k];
        float h0 = hs[tx][k], h1 = hs[tx + 16][k];
        a00 += t0 * h0; a01 += t0 * h1;
        a10 += t1 * h0; a11 += t1 * h1;
    }
    int i0 = ib + ty, i1 = ib + ty + 16;
    int j0 = jb + tx, j1 = jb + tx + 16;
    if (i0 < ND) {
        if (j0 < ND) out[(size_t)i0 * ND + j0] = a00;
        if (j1 < ND) out[(size_t)i0 * ND + j1] = a01;
    }
    if (i1 < ND) {
        if (j0 < ND) out[(size_t)i1 * ND + j0] = a10;
        if (j1 < ND) out[(size_t)i1 * ND + j1] = a11;
    }
}

// ---------------- launch ----------------
extern "C" void kernel_launch(void* const* d_in, const int* in_sizes, int n_in,
                              void* d_out, int out_size) {
    (void)in_sizes; (void)n_in; (void)out_size;
    const float* x  = (const float*)d_in[0];
    const int*   ei = (const int*)  d_in[1];
    const float* W1 = (const float*)d_in[2];
    const float* b1 = (const float*)d_in[3];
    const float* W2 = (const float*)d_in[4];
    const float* b2 = (const float*)d_in[5];
    const float* P  = (const float*)d_in[6];
    float* out = (float*)d_out;

    const int* src = ei;
    const int* dst = ei + NE;

    k_init <<<(NN + 255) / 256, 256>>>();
    k_prep2<<<NE / 256, 256>>>(src, dst);

    // layer 1 + layer-2 GEMM fused into the gather
    k_gemm1    <<<(NN + 255) / 256, 256>>>(x, W1);
    k_gather_g2<<<(NN * 4 + 255) / 256, 256>>>(W2, b1);

    // layer 2 aggregation (drug rows only)
    k_edge2<<<256, 256>>>();

    // decoder
    k_pred1<<<(ND * HID) / 256, 256>>>(P, b2);
    k_out  <<<dim3((ND + 31) / 32, (ND + 31) / 32), 256>>>(out);
}